// round 14
// baseline (speedup 1.0000x reference)
#include <cuda_runtime.h>
#include <cstdint>

// Problem constants
#define BB 16
#define LL 512
#define DD 768
#define HH 12
#define UU 384
#define NH 6
#define HD 64
#define KP 384
#define RR 128        // L - K  (merged count == unpreserved count)
#define LH 256        // L/2
#define OT 386        // output tokens per batch

// ---------------- device scratch (static, allocation-free) ----------------
__device__ float              g_imp[BB * LL];
__device__ float              g_invn[BB * LL];
__device__ int                g_unp[BB * RR];
__device__ unsigned long long g_nodekey[BB * LH];
__device__ int                g_unm[BB * RR];
__device__ int                g_csr_off[BB * (LH + 1)];
__device__ int                g_csr_src[BB * RR];
__device__ float              g_m[BB * NH * DD];
__device__ float              g_cb[BB * NH];
__device__ float              g_logits[BB * NH * RR];
__device__ float              g_y[BB * NH * DD];
__device__ float              g_ctxp[4][BB * UU];

__device__ __forceinline__ unsigned ford(float f) {
    unsigned u = __float_as_uint(f);
    return (u & 0x80000000u) ? ~u : (u | 0x80000000u);
}

// packed fp32x2 FMA (sm_100+): acc = a*b + acc, two lanes per instruction
__device__ __forceinline__ void ffma2(unsigned long long& acc,
                                      unsigned long long a, unsigned long long b) {
    asm("fma.rn.f32x2 %0, %1, %2, %0;" : "+l"(acc) : "l"(a), "l"(b));
}
__device__ __forceinline__ unsigned long long pk2(float x, float y) {
    unsigned long long r;
    asm("mov.b64 %0, {%1, %2};" : "=l"(r) : "f"(x), "f"(y));
    return r;
}
__device__ __forceinline__ float lo32(unsigned long long v) {
    return __uint_as_float((unsigned)v);
}
__device__ __forceinline__ float hi32(unsigned long long v) {
    return __uint_as_float((unsigned)(v >> 32));
}

// ---------------- K0: init accumulators (must run every replay) -----------
__global__ void k_init() {
    int i = blockIdx.x * blockDim.x + threadIdx.x;
    if (i < BB * LL) g_imp[i] = 0.f;
    if (i < BB * LH) g_nodekey[i] = 0ull;
}

// ---------------- importance = column sums, diag removed ------------------
__global__ void k_importance(const float* __restrict__ sc) {
    int b = blockIdx.z, h = blockIdx.y, chunk = blockIdx.x;
    int j0 = threadIdx.x * 4;
    const float* base = sc + (((size_t)b * HH + h) * LL + (size_t)chunk * 64) * LL;
    int i0 = chunk * 64;
    float a0 = 0.f, a1 = 0.f, a2 = 0.f, a3 = 0.f;
#pragma unroll 4
    for (int i = 0; i < 64; i++) {
        float4 v = *(const float4*)(base + (size_t)i * LL + j0);
        int gi = i0 + i;
        if (gi == j0)     v.x = 0.f;
        if (gi == j0 + 1) v.y = 0.f;
        if (gi == j0 + 2) v.z = 0.f;
        if (gi == j0 + 3) v.w = 0.f;
        a0 += v.x; a1 += v.y; a2 += v.z; a3 += v.w;
    }
    float* ip = g_imp + b * LL + j0;
    atomicAdd(ip + 0, a0); atomicAdd(ip + 1, a1);
    atomicAdd(ip + 2, a2); atomicAdd(ip + 3, a3);
}

// ---------------- per-token inverse L2 norms -------------------------------
__global__ void k_invnorm(const float* __restrict__ hid) {
    int warp = threadIdx.x >> 5, lane = threadIdx.x & 31;
    int row = blockIdx.x * 8 + warp;
    int b = blockIdx.y;
    const float4* p = (const float4*)(hid + ((size_t)b * LL + row) * DD);
    float s = 0.f;
#pragma unroll
    for (int it = 0; it < 6; it++) {
        float4 v = p[lane + it * 32];
        s += v.x * v.x + v.y * v.y + v.z * v.z + v.w * v.w;
    }
    for (int off = 16; off; off >>= 1) s += __shfl_xor_sync(0xffffffffu, s, off);
    if (lane == 0) g_invn[b * LL + row] = rsqrtf(s);
}

// ---------------- top-K -> unpreserved idx (ascending) ---------------------
// Rank-by-count with index tiebreak == lax.top_k; ballot-based compaction.
__global__ void k_topk() {
    int b = blockIdx.x, t = threadIdx.x;
    __shared__ __align__(16) unsigned long long keys[LL];
    __shared__ int wsum[16];
    float v = g_imp[b * LL + t];
    unsigned long long key =
        ((unsigned long long)ford(v) << 32) | (unsigned)(0xFFFFFFFFu - t);
    keys[t] = key;
    __syncthreads();
    int rank = 0;
    const ulonglong2* k2 = (const ulonglong2*)keys;
#pragma unroll 8
    for (int x = 0; x < LL / 2; x++) {
        ulonglong2 kk = k2[x];
        rank += (kk.x > key) + (kk.y > key);
    }
    int unp = (rank >= KP) ? 1 : 0;
    unsigned bal = __ballot_sync(0xffffffffu, unp);
    int lane = t & 31, wp = t >> 5;
    if (lane == 0) wsum[wp] = __popc(bal);
    __syncthreads();
    if (unp) {
        int base = 0;
        for (int w = 0; w < wp; w++) base += wsum[w];
        int pos = base + __popc(bal & ((1u << lane) - 1));
        g_unp[b * RR + pos] = t;
    }
}

// ---------------- cosine-sim GEMM + row max/argmax -------------------------
// 64x64 tile, 256 threads, 4x4 micro-tile in packed fp32x2 (exact fp32 fma
// per element — rank decisions identical to scalar). Row argmax via atomicMax.
__global__ void k_sim(const float* __restrict__ hid) {
    int b = blockIdx.z, i0 = blockIdx.y * 64, j0 = blockIdx.x * 64;
    __shared__ __align__(16) float As[16][68];
    __shared__ __align__(16) float Bs[16][68];
    int tid = threadIdx.x;
    int tx = tid & 15, ty = tid >> 4;
    int lrow = tid >> 2, lseg = tid & 3;
    const float* base = hid + (size_t)b * LL * DD;
    float ia = g_invn[b * LL + 2 * (i0 + lrow)];
    float ib = g_invn[b * LL + 2 * (j0 + lrow) + 1];
    const float* arow = base + (size_t)(2 * (i0 + lrow)) * DD + lseg * 4;
    const float* brow = base + (size_t)(2 * (j0 + lrow) + 1) * DD + lseg * 4;

    // acc2[p][q]: p=0 packs rows (4ty, 4ty+1), p=1 packs rows (4ty+2, 4ty+3)
    unsigned long long acc2[2][4];
#pragma unroll
    for (int p = 0; p < 2; p++)
#pragma unroll
        for (int q = 0; q < 4; q++) acc2[p][q] = 0ull;

    for (int k0 = 0; k0 < DD; k0 += 16) {
        float4 av = *(const float4*)(arow + k0);
        float4 bv = *(const float4*)(brow + k0);
        __syncthreads();
        As[lseg * 4 + 0][lrow] = av.x * ia;
        As[lseg * 4 + 1][lrow] = av.y * ia;
        As[lseg * 4 + 2][lrow] = av.z * ia;
        As[lseg * 4 + 3][lrow] = av.w * ia;
        Bs[lseg * 4 + 0][lrow] = bv.x * ib;
        Bs[lseg * 4 + 1][lrow] = bv.y * ib;
        Bs[lseg * 4 + 2][lrow] = bv.z * ib;
        Bs[lseg * 4 + 3][lrow] = bv.w * ib;
        __syncthreads();
#pragma unroll
        for (int kk = 0; kk < 16; kk++) {
            ulonglong2 ap = *(const ulonglong2*)&As[kk][ty * 4];  // (a0,a1),(a2,a3)
            float4 c4 = *(const float4*)&Bs[kk][tx * 4];
            unsigned long long c0 = pk2(c4.x, c4.x);
            unsigned long long c1 = pk2(c4.y, c4.y);
            unsigned long long c2 = pk2(c4.z, c4.z);
            unsigned long long c3 = pk2(c4.w, c4.w);
            ffma2(acc2[0][0], ap.x, c0); ffma2(acc2[1][0], ap.y, c0);
            ffma2(acc2[0][1], ap.x, c1); ffma2(acc2[1][1], ap.y, c1);
            ffma2(acc2[0][2], ap.x, c2); ffma2(acc2[1][2], ap.y, c2);
            ffma2(acc2[0][3], ap.x, c3); ffma2(acc2[1][3], ap.y, c3);
        }
    }
    // per-row max/argmax (tie -> smaller j, matching jnp.argmax)
#pragma unroll
    for (int r = 0; r < 4; r++) {
        int p = r >> 1;
        float v0, v1, v2, v3;
        if (r & 1) {
            v0 = hi32(acc2[p][0]); v1 = hi32(acc2[p][1]);
            v2 = hi32(acc2[p][2]); v3 = hi32(acc2[p][3]);
        } else {
            v0 = lo32(acc2[p][0]); v1 = lo32(acc2[p][1]);
            v2 = lo32(acc2[p][2]); v3 = lo32(acc2[p][3]);
        }
        float best = v0; int bc = 0;
        if (v1 > best) { best = v1; bc = 1; }
        if (v2 > best) { best = v2; bc = 2; }
        if (v3 > best) { best = v3; bc = 3; }
        int j = j0 + tx * 4 + bc;
        unsigned long long key =
            ((unsigned long long)ford(best) << 32) | (unsigned)(255 - j);
        for (int off = 8; off; off >>= 1) {
            unsigned long long o = __shfl_xor_sync(0xffffffffu, key, off);
            if (o > key) key = o;
        }
        if (tx == 0) atomicMax(&g_nodekey[b * LH + i0 + ty * 4 + r], key);
    }
}

// ---------------- edge argsort + CSR inverse map ---------------------------
// rank<128 -> src (build dst->src CSR lists in smem), else unm.
__global__ void k_edges() {
    int b = blockIdx.x, i = threadIdx.x;
    __shared__ __align__(16) unsigned long long ek[LH];
    __shared__ int scnt[LH];
    __shared__ int soff[LH];
    __shared__ int scur[LH];
    unsigned long long nk = g_nodekey[b * LH + i];
    int nidx = 255 - (int)(unsigned)(nk & 0xFFFFFFFFull);
    unsigned long long key = (nk & 0xFFFFFFFF00000000ull) | (unsigned)(255 - i);
    ek[i] = key;
    scnt[i] = 0;
    scur[i] = 0;
    __syncthreads();
    int rank = 0;
    const ulonglong2* k2 = (const ulonglong2*)ek;
#pragma unroll 8
    for (int x = 0; x < LH / 2; x++) {
        ulonglong2 kk = k2[x];
        rank += (kk.x > key) + (kk.y > key);
    }
    bool issrc = (rank < RR);
    if (issrc) atomicAdd(&scnt[nidx], 1);
    else g_unm[b * RR + (rank - RR)] = i;
    __syncthreads();
    int off = 0;
    for (int x = 0; x < i; x++) off += scnt[x];
    soff[i] = off;
    g_csr_off[b * (LH + 1) + i] = off;
    if (i == 0) g_csr_off[b * (LH + 1) + LH] = RR;
    __syncthreads();
    if (issrc) {
        int slot = atomicAdd(&scur[nidx], 1);
        g_csr_src[b * RR + soff[nidx] + slot] = i;
    }
}

// ---------------- assemble: class + unm copies -----------------------------
__global__ void k_copy(const float* __restrict__ hid, float* __restrict__ out) {
    int b = blockIdx.y, v = blockIdx.x;                  // 0..128
    int srow = (v == 0) ? 0 : 2 * g_unm[b * RR + (v - 1)];
    const float4* s = (const float4*)(hid + ((size_t)b * LL + srow) * DD);
    float4* d = (float4*)(out + ((size_t)b * OT + v) * DD);
    d[threadIdx.x] = s[threadIdx.x];
}

// ---------------- merged dst tokens via CSR gather (no atomics) ------------
__global__ void k_merge2(const float* __restrict__ hid, float* __restrict__ out) {
    int b = blockIdx.y, j = blockIdx.x;                  // 0..255
    int o0 = g_csr_off[b * (LH + 1) + j];
    int o1 = g_csr_off[b * (LH + 1) + j + 1];
    int d0 = threadIdx.x * 4;
    const float* dx = hid + ((size_t)b * LL + 2 * j + 1) * DD + d0;
    float4 a = *(const float4*)dx;
    for (int p = o0; p < o1; p++) {
        int s = g_csr_src[b * RR + p];
        float4 v = *(const float4*)(hid + ((size_t)b * LL + 2 * s) * DD + d0);
        a.x += v.x; a.y += v.y; a.z += v.z; a.w += v.w;
    }
    float inv = 1.0f / (float)(1 + (o1 - o0));
    a.x *= inv; a.y *= inv; a.z *= inv; a.w *= inv;
    *(float4*)(out + ((size_t)b * OT + 129 + j) * DD + d0) = a;
}

// ---------------- attention: q_h + m_h + cbias fused, grid (6,16) ----------
__global__ void k_qm(const float* __restrict__ hid, const float* __restrict__ Wq,
                     const float* __restrict__ bq, const float* __restrict__ Wk,
                     const float* __restrict__ bk) {
    int h = blockIdx.x, b = blockIdx.y, t = threadIdx.x;     // 256 threads
    __shared__ float cls[DD];
    __shared__ float qp[4][HD];
    __shared__ float sq[HD];
    __shared__ float sp[HD];
    cls[t] = hid[(size_t)b * LL * DD + t];
    cls[t + 256] = hid[(size_t)b * LL * DD + 256 + t];
    cls[t + 512] = hid[(size_t)b * LL * DD + 512 + t];
    __syncthreads();
    // stage 1: q_h[u] = bq + cls . Wq[:, h*64+u], k split 4 ways
    {
        int u = t & 63, kq = t >> 6;
        float p = 0.f;
        const float* wcol = Wq + (size_t)(h * HD + u);
#pragma unroll 4
        for (int k = kq * 192; k < kq * 192 + 192; k++)
            p += cls[k] * wcol[(size_t)k * UU];
        qp[kq][u] = p;
    }
    __syncthreads();
    if (t < HD) {
        float q = bq[h * HD + t] + qp[0][t] + qp[1][t] + qp[2][t] + qp[3][t];
        sq[t] = q;
        sp[t] = q * bk[h * HD + t];
    }
    __syncthreads();
    // stage 2: m[row] = Wk[row, h*64:h*64+64] . q_h, rows t, t+256, t+512
#pragma unroll
    for (int rr = 0; rr < 3; rr++) {
        int row = t + rr * 256;
        const float* wrow = Wk + (size_t)row * UU + h * HD;
        float acc = 0.f;
#pragma unroll
        for (int u = 0; u < HD; u += 4) {
            float4 wv = *(const float4*)(wrow + u);
            acc += wv.x * sq[u] + wv.y * sq[u + 1] + wv.z * sq[u + 2] + wv.w * sq[u + 3];
        }
        g_m[((size_t)b * NH + h) * DD + row] = acc;
    }
    if (t == 0) {
        float c = 0.f;
        for (int u = 0; u < HD; u++) c += sp[u];
        g_cb[b * NH + h] = c;
    }
}

// logits[b,h,t] = (x_t . m_bh + cbias) / 8      one warp per (b,t)
__global__ void k_logits(const float* __restrict__ hid) {
    int w = (blockIdx.x * blockDim.x + threadIdx.x) >> 5;
    int lane = threadIdx.x & 31;
    if (w >= BB * RR) return;
    int b = w >> 7, t = w & 127;
    int row = g_unp[b * RR + t];
    const float* x = hid + ((size_t)b * LL + row) * DD;
    const float* m = g_m + (size_t)b * NH * DD;
    float acc[NH] = {};
    for (int k = lane; k < DD; k += 32) {
        float xv = x[k];
#pragma unroll
        for (int h = 0; h < NH; h++) acc[h] += xv * m[h * DD + k];
    }
#pragma unroll
    for (int h = 0; h < NH; h++)
        for (int off = 16; off; off >>= 1) acc[h] += __shfl_xor_sync(0xffffffffu, acc[h], off);
    if (lane == 0) {
#pragma unroll
        for (int h = 0; h < NH; h++)
            g_logits[((size_t)b * NH + h) * RR + t] = (acc[h] + g_cb[b * NH + h]) * 0.125f;
    }
}

// softmax over 128 keys, then y[b,h,:] = sum_t w_t * x_t   grid (6,16), 256 thr
__global__ void k_smax_y(const float* __restrict__ hid) {
    int h = blockIdx.x, b = blockIdx.y, t = threadIdx.x;
    __shared__ float w[RR];
    __shared__ int su[RR];
    __shared__ float red[8];
    if (t < RR) {
        w[t] = g_logits[((size_t)b * NH + h) * RR + t];
        su[t] = g_unp[b * RR + t];
    }
    __syncthreads();
    if (t < RR) {
        float m = w[t];
        for (int off = 16; off; off >>= 1) m = fmaxf(m, __shfl_xor_sync(0xffffffffu, m, off));
        if ((t & 31) == 0) red[t >> 5] = m;
    }
    __syncthreads();
    float mx = fmaxf(fmaxf(red[0], red[1]), fmaxf(red[2], red[3]));
    float e = 0.f;
    if (t < RR) e = expf(w[t] - mx);
    float s = e;
    for (int off = 16; off; off >>= 1) s += __shfl_xor_sync(0xffffffffu, s, off);
    if (t < RR && (t & 31) == 0) red[4 + (t >> 5)] = s;
    __syncthreads();
    float tot = red[4] + red[5] + red[6] + red[7];
    if (t < RR) w[t] = e / tot;
    __syncthreads();
    for (int d = t; d < DD; d += 256) {
        float acc = 0.f;
#pragma unroll 4
        for (int tt = 0; tt < RR; tt++)
            acc += w[tt] * hid[((size_t)b * LL + su[tt]) * DD + d];
        g_y[((size_t)b * NH + h) * DD + d] = acc;
    }
}

// ctx partials: grid (16, 4), 384 threads; chunk c covers 192 of the 768 d's.
__global__ void k_ctx(const float* __restrict__ Wv, const float* __restrict__ bv) {
    int b = blockIdx.x, c = blockIdx.y, u = threadIdx.x;
    __shared__ float sy[NH * 192];
    for (int i = u; i < NH * 192; i += UU) {
        int h = i / 192, dd = i % 192;
        sy[i] = g_y[((size_t)b * NH + h) * DD + c * 192 + dd];
    }
    __syncthreads();
    int h = u >> 6;
    float acc = (c == 0) ? bv[u] : 0.f;
    const float* wv = Wv + (size_t)(c * 192) * UU + u;
#pragma unroll 4
    for (int dd = 0; dd < 192; dd++) acc += sy[h * 192 + dd] * wv[(size_t)dd * UU];
    g_ctxp[c][b * UU + u] = acc;
}

// new_token: grid (16, 6), 128 threads; sums 4 ctx partials, then GEMV.
__global__ void k_newtok(const float* __restrict__ Wo, const float* __restrict__ bo,
                         float* __restrict__ out) {
    int b = blockIdx.x, seg = blockIdx.y, t = threadIdx.x;
    __shared__ float sc[UU];
    for (int i = t; i < UU; i += 128)
        sc[i] = g_ctxp[0][b * UU + i] + g_ctxp[1][b * UU + i] +
                g_ctxp[2][b * UU + i] + g_ctxp[3][b * UU + i];
    __syncthreads();
    int d = seg * 128 + t;
    float acc = bo[d];
#pragma unroll 4
    for (int u = 0; u < UU; u++) acc += sc[u] * Wo[(size_t)u * DD + d];
    out[((size_t)b * OT + 385) * DD + d] = acc;
}

// ---------------- launch ----------------------------------------------------
extern "C" void kernel_launch(void* const* d_in, const int* in_sizes, int n_in,
                              void* d_out, int out_size) {
    (void)in_sizes; (void)n_in; (void)out_size;
    const float* hid = (const float*)d_in[0];
    const float* sc  = (const float*)d_in[1];
    const float* Wq  = (const float*)d_in[2];
    const float* bq  = (const float*)d_in[3];
    const float* Wk  = (const float*)d_in[4];
    const float* bk  = (const float*)d_in[5];
    const float* Wv  = (const float*)d_in[6];
    const float* bv  = (const float*)d_in[7];
    const float* Wo  = (const float*)d_in[8];
    const float* bo  = (const float*)d_in[9];
    float* out = (float*)d_out;

    k_init<<<32, 256>>>();
    k_importance<<<dim3(8, HH, BB), 128>>>(sc);
    k_invnorm<<<dim3(64, BB), 256>>>(hid);
    k_topk<<<BB, 512>>>();
    k_sim<<<dim3(4, 4, BB), 256>>>(hid);
    k_edges<<<BB, 256>>>();
    k_copy<<<dim3(129, BB), 192>>>(hid, out);
    k_merge2<<<dim3(LH, BB), 192>>>(hid, out);
    k_qm<<<dim3(NH, BB), 256>>>(hid, Wq, bq, Wk, bk);
    k_logits<<<256, 256>>>(hid);
    k_smax_y<<<dim3(NH, BB), 256>>>(hid);
    k_ctx<<<dim3(BB, 4), 384>>>(Wv, bv);
    k_newtok<<<dim3(BB, 6), 128>>>(Wo, bo, out);
}

// round 15
// speedup vs baseline: 1.0001x; 1.0001x over previous
#include <cuda_runtime.h>
#include <cstdint>

// Problem constants
#define BB 16
#define LL 512
#define DD 768
#define HH 12
#define UU 384
#define NH 6
#define HD 64
#define KP 384
#define RR 128        // L - K  (merged count == unpreserved count)
#define LH 256        // L/2
#define OT 386        // output tokens per batch

// ---------------- device scratch (static, allocation-free) ----------------
__device__ float              g_imp[BB * LL];
__device__ float              g_invn[BB * LL];
__device__ int                g_unp[BB * RR];
__device__ unsigned long long g_nodekey[BB * LH];
__device__ int                g_unm[BB * RR];
__device__ int                g_csr_off[BB * (LH + 1)];
__device__ int                g_csr_src[BB * RR];
__device__ float              g_m[BB * NH * DD];
__device__ float              g_cb[BB * NH];
__device__ float              g_logits[BB * NH * RR];
__device__ float              g_y[BB * NH * DD];
__device__ float              g_ctxp[4][BB * UU];

__device__ __forceinline__ unsigned ford(float f) {
    unsigned u = __float_as_uint(f);
    return (u & 0x80000000u) ? ~u : (u | 0x80000000u);
}

// packed fp32x2 FMA (sm_100+): acc = a*b + acc, two lanes per instruction
__device__ __forceinline__ void ffma2(unsigned long long& acc,
                                      unsigned long long a, unsigned long long b) {
    asm("fma.rn.f32x2 %0, %1, %2, %0;" : "+l"(acc) : "l"(a), "l"(b));
}
__device__ __forceinline__ unsigned long long pk2(float x, float y) {
    unsigned long long r;
    asm("mov.b64 %0, {%1, %2};" : "=l"(r) : "f"(x), "f"(y));
    return r;
}
__device__ __forceinline__ float lo32(unsigned long long v) {
    return __uint_as_float((unsigned)v);
}
__device__ __forceinline__ float hi32(unsigned long long v) {
    return __uint_as_float((unsigned)(v >> 32));
}

// ---------------- K0: init accumulators (must run every replay) -----------
__global__ void k_init() {
    int i = blockIdx.x * blockDim.x + threadIdx.x;
    if (i < BB * LL) g_imp[i] = 0.f;
    if (i < BB * LH) g_nodekey[i] = 0ull;
}

// ---------------- importance = column sums, diag removed ------------------
__global__ void k_importance(const float* __restrict__ sc) {
    int b = blockIdx.z, h = blockIdx.y, chunk = blockIdx.x;
    int j0 = threadIdx.x * 4;
    const float* base = sc + (((size_t)b * HH + h) * LL + (size_t)chunk * 64) * LL;
    int i0 = chunk * 64;
    float a0 = 0.f, a1 = 0.f, a2 = 0.f, a3 = 0.f;
#pragma unroll 4
    for (int i = 0; i < 64; i++) {
        float4 v = *(const float4*)(base + (size_t)i * LL + j0);
        int gi = i0 + i;
        if (gi == j0)     v.x = 0.f;
        if (gi == j0 + 1) v.y = 0.f;
        if (gi == j0 + 2) v.z = 0.f;
        if (gi == j0 + 3) v.w = 0.f;
        a0 += v.x; a1 += v.y; a2 += v.z; a3 += v.w;
    }
    float* ip = g_imp + b * LL + j0;
    atomicAdd(ip + 0, a0); atomicAdd(ip + 1, a1);
    atomicAdd(ip + 2, a2); atomicAdd(ip + 3, a3);
}

// ---------------- per-token inverse L2 norms -------------------------------
__global__ void k_invnorm(const float* __restrict__ hid) {
    int warp = threadIdx.x >> 5, lane = threadIdx.x & 31;
    int row = blockIdx.x * 8 + warp;
    int b = blockIdx.y;
    const float4* p = (const float4*)(hid + ((size_t)b * LL + row) * DD);
    float s = 0.f;
#pragma unroll
    for (int it = 0; it < 6; it++) {
        float4 v = p[lane + it * 32];
        s += v.x * v.x + v.y * v.y + v.z * v.z + v.w * v.w;
    }
    for (int off = 16; off; off >>= 1) s += __shfl_xor_sync(0xffffffffu, s, off);
    if (lane == 0) g_invn[b * LL + row] = rsqrtf(s);
}

// ---------------- top-K -> unpreserved idx (ascending) ---------------------
// Rank-by-count with index tiebreak == lax.top_k; ballot-based compaction.
__global__ void k_topk() {
    int b = blockIdx.x, t = threadIdx.x;
    __shared__ __align__(16) unsigned long long keys[LL];
    __shared__ int wsum[16];
    float v = g_imp[b * LL + t];
    unsigned long long key =
        ((unsigned long long)ford(v) << 32) | (unsigned)(0xFFFFFFFFu - t);
    keys[t] = key;
    __syncthreads();
    int rank = 0;
    const ulonglong2* k2 = (const ulonglong2*)keys;
#pragma unroll 8
    for (int x = 0; x < LL / 2; x++) {
        ulonglong2 kk = k2[x];
        rank += (kk.x > key) + (kk.y > key);
    }
    int unp = (rank >= KP) ? 1 : 0;
    unsigned bal = __ballot_sync(0xffffffffu, unp);
    int lane = t & 31, wp = t >> 5;
    if (lane == 0) wsum[wp] = __popc(bal);
    __syncthreads();
    if (unp) {
        int base = 0;
        for (int w = 0; w < wp; w++) base += wsum[w];
        int pos = base + __popc(bal & ((1u << lane) - 1));
        g_unp[b * RR + pos] = t;
    }
}

// ---------------- cosine-sim GEMM + row max/argmax -------------------------
// 64x64 tile, 256 threads, 4x4 micro-tile in packed fp32x2 (exact fp32 fma
// per element — rank decisions identical to scalar). Row argmax via atomicMax.
__global__ void k_sim(const float* __restrict__ hid) {
    int b = blockIdx.z, i0 = blockIdx.y * 64, j0 = blockIdx.x * 64;
    __shared__ __align__(16) float As[16][68];
    __shared__ __align__(16) float Bs[16][68];
    int tid = threadIdx.x;
    int tx = tid & 15, ty = tid >> 4;
    int lrow = tid >> 2, lseg = tid & 3;
    const float* base = hid + (size_t)b * LL * DD;
    float ia = g_invn[b * LL + 2 * (i0 + lrow)];
    float ib = g_invn[b * LL + 2 * (j0 + lrow) + 1];
    const float* arow = base + (size_t)(2 * (i0 + lrow)) * DD + lseg * 4;
    const float* brow = base + (size_t)(2 * (j0 + lrow) + 1) * DD + lseg * 4;

    // acc2[p][q]: p=0 packs rows (4ty, 4ty+1), p=1 packs rows (4ty+2, 4ty+3)
    unsigned long long acc2[2][4];
#pragma unroll
    for (int p = 0; p < 2; p++)
#pragma unroll
        for (int q = 0; q < 4; q++) acc2[p][q] = 0ull;

    for (int k0 = 0; k0 < DD; k0 += 16) {
        float4 av = *(const float4*)(arow + k0);
        float4 bv = *(const float4*)(brow + k0);
        __syncthreads();
        As[lseg * 4 + 0][lrow] = av.x * ia;
        As[lseg * 4 + 1][lrow] = av.y * ia;
        As[lseg * 4 + 2][lrow] = av.z * ia;
        As[lseg * 4 + 3][lrow] = av.w * ia;
        Bs[lseg * 4 + 0][lrow] = bv.x * ib;
        Bs[lseg * 4 + 1][lrow] = bv.y * ib;
        Bs[lseg * 4 + 2][lrow] = bv.z * ib;
        Bs[lseg * 4 + 3][lrow] = bv.w * ib;
        __syncthreads();
#pragma unroll
        for (int kk = 0; kk < 16; kk++) {
            ulonglong2 ap = *(const ulonglong2*)&As[kk][ty * 4];  // (a0,a1),(a2,a3)
            float4 c4 = *(const float4*)&Bs[kk][tx * 4];
            unsigned long long c0 = pk2(c4.x, c4.x);
            unsigned long long c1 = pk2(c4.y, c4.y);
            unsigned long long c2 = pk2(c4.z, c4.z);
            unsigned long long c3 = pk2(c4.w, c4.w);
            ffma2(acc2[0][0], ap.x, c0); ffma2(acc2[1][0], ap.y, c0);
            ffma2(acc2[0][1], ap.x, c1); ffma2(acc2[1][1], ap.y, c1);
            ffma2(acc2[0][2], ap.x, c2); ffma2(acc2[1][2], ap.y, c2);
            ffma2(acc2[0][3], ap.x, c3); ffma2(acc2[1][3], ap.y, c3);
        }
    }
    // per-row max/argmax (tie -> smaller j, matching jnp.argmax)
#pragma unroll
    for (int r = 0; r < 4; r++) {
        int p = r >> 1;
        float v0, v1, v2, v3;
        if (r & 1) {
            v0 = hi32(acc2[p][0]); v1 = hi32(acc2[p][1]);
            v2 = hi32(acc2[p][2]); v3 = hi32(acc2[p][3]);
        } else {
            v0 = lo32(acc2[p][0]); v1 = lo32(acc2[p][1]);
            v2 = lo32(acc2[p][2]); v3 = lo32(acc2[p][3]);
        }
        float best = v0; int bc = 0;
        if (v1 > best) { best = v1; bc = 1; }
        if (v2 > best) { best = v2; bc = 2; }
        if (v3 > best) { best = v3; bc = 3; }
        int j = j0 + tx * 4 + bc;
        unsigned long long key =
            ((unsigned long long)ford(best) << 32) | (unsigned)(255 - j);
        for (int off = 8; off; off >>= 1) {
            unsigned long long o = __shfl_xor_sync(0xffffffffu, key, off);
            if (o > key) key = o;
        }
        if (tx == 0) atomicMax(&g_nodekey[b * LH + i0 + ty * 4 + r], key);
    }
}

// ---------------- edge argsort + CSR inverse map ---------------------------
// rank<128 -> src (build dst->src CSR lists in smem), else unm.
__global__ void k_edges() {
    int b = blockIdx.x, i = threadIdx.x;
    __shared__ __align__(16) unsigned long long ek[LH];
    __shared__ int scnt[LH];
    __shared__ int soff[LH];
    __shared__ int scur[LH];
    unsigned long long nk = g_nodekey[b * LH + i];
    int nidx = 255 - (int)(unsigned)(nk & 0xFFFFFFFFull);
    unsigned long long key = (nk & 0xFFFFFFFF00000000ull) | (unsigned)(255 - i);
    ek[i] = key;
    scnt[i] = 0;
    scur[i] = 0;
    __syncthreads();
    int rank = 0;
    const ulonglong2* k2 = (const ulonglong2*)ek;
#pragma unroll 8
    for (int x = 0; x < LH / 2; x++) {
        ulonglong2 kk = k2[x];
        rank += (kk.x > key) + (kk.y > key);
    }
    bool issrc = (rank < RR);
    if (issrc) atomicAdd(&scnt[nidx], 1);
    else g_unm[b * RR + (rank - RR)] = i;
    __syncthreads();
    int off = 0;
    for (int x = 0; x < i; x++) off += scnt[x];
    soff[i] = off;
    g_csr_off[b * (LH + 1) + i] = off;
    if (i == 0) g_csr_off[b * (LH + 1) + LH] = RR;
    __syncthreads();
    if (issrc) {
        int slot = atomicAdd(&scur[nidx], 1);
        g_csr_src[b * RR + soff[nidx] + slot] = i;
    }
}

// ---------------- assemble: class + unm copies -----------------------------
__global__ void k_copy(const float* __restrict__ hid, float* __restrict__ out) {
    int b = blockIdx.y, v = blockIdx.x;                  // 0..128
    int srow = (v == 0) ? 0 : 2 * g_unm[b * RR + (v - 1)];
    const float4* s = (const float4*)(hid + ((size_t)b * LL + srow) * DD);
    float4* d = (float4*)(out + ((size_t)b * OT + v) * DD);
    d[threadIdx.x] = s[threadIdx.x];
}

// ---------------- merged dst tokens via CSR gather (no atomics) ------------
__global__ void k_merge2(const float* __restrict__ hid, float* __restrict__ out) {
    int b = blockIdx.y, j = blockIdx.x;                  // 0..255
    int o0 = g_csr_off[b * (LH + 1) + j];
    int o1 = g_csr_off[b * (LH + 1) + j + 1];
    int d0 = threadIdx.x * 4;
    const float* dx = hid + ((size_t)b * LL + 2 * j + 1) * DD + d0;
    float4 a = *(const float4*)dx;
    for (int p = o0; p < o1; p++) {
        int s = g_csr_src[b * RR + p];
        float4 v = *(const float4*)(hid + ((size_t)b * LL + 2 * s) * DD + d0);
        a.x += v.x; a.y += v.y; a.z += v.z; a.w += v.w;
    }
    float inv = 1.0f / (float)(1 + (o1 - o0));
    a.x *= inv; a.y *= inv; a.z *= inv; a.w *= inv;
    *(float4*)(out + ((size_t)b * OT + 129 + j) * DD + d0) = a;
}

// ---------------- attention: q_h + m_h + cbias fused, grid (6,16) ----------
__global__ void k_qm(const float* __restrict__ hid, const float* __restrict__ Wq,
                     const float* __restrict__ bq, const float* __restrict__ Wk,
                     const float* __restrict__ bk) {
    int h = blockIdx.x, b = blockIdx.y, t = threadIdx.x;     // 256 threads
    __shared__ float cls[DD];
    __shared__ float qp[4][HD];
    __shared__ float sq[HD];
    __shared__ float sp[HD];
    cls[t] = hid[(size_t)b * LL * DD + t];
    cls[t + 256] = hid[(size_t)b * LL * DD + 256 + t];
    cls[t + 512] = hid[(size_t)b * LL * DD + 512 + t];
    __syncthreads();
    // stage 1: q_h[u] = bq + cls . Wq[:, h*64+u], k split 4 ways
    {
        int u = t & 63, kq = t >> 6;
        float p = 0.f;
        const float* wcol = Wq + (size_t)(h * HD + u);
#pragma unroll 4
        for (int k = kq * 192; k < kq * 192 + 192; k++)
            p += cls[k] * wcol[(size_t)k * UU];
        qp[kq][u] = p;
    }
    __syncthreads();
    if (t < HD) {
        float q = bq[h * HD + t] + qp[0][t] + qp[1][t] + qp[2][t] + qp[3][t];
        sq[t] = q;
        sp[t] = q * bk[h * HD + t];
    }
    __syncthreads();
    // stage 2: m[row] = Wk[row, h*64:h*64+64] . q_h, rows t, t+256, t+512
#pragma unroll
    for (int rr = 0; rr < 3; rr++) {
        int row = t + rr * 256;
        const float* wrow = Wk + (size_t)row * UU + h * HD;
        float acc = 0.f;
#pragma unroll
        for (int u = 0; u < HD; u += 4) {
            float4 wv = *(const float4*)(wrow + u);
            acc += wv.x * sq[u] + wv.y * sq[u + 1] + wv.z * sq[u + 2] + wv.w * sq[u + 3];
        }
        g_m[((size_t)b * NH + h) * DD + row] = acc;
    }
    if (t == 0) {
        float c = 0.f;
        for (int u = 0; u < HD; u++) c += sp[u];
        g_cb[b * NH + h] = c;
    }
}

// logits[b,h,t] = (x_t . m_bh + cbias) / 8      one warp per (b,t)
__global__ void k_logits(const float* __restrict__ hid) {
    int w = (blockIdx.x * blockDim.x + threadIdx.x) >> 5;
    int lane = threadIdx.x & 31;
    if (w >= BB * RR) return;
    int b = w >> 7, t = w & 127;
    int row = g_unp[b * RR + t];
    const float* x = hid + ((size_t)b * LL + row) * DD;
    const float* m = g_m + (size_t)b * NH * DD;
    float acc[NH] = {};
    for (int k = lane; k < DD; k += 32) {
        float xv = x[k];
#pragma unroll
        for (int h = 0; h < NH; h++) acc[h] += xv * m[h * DD + k];
    }
#pragma unroll
    for (int h = 0; h < NH; h++)
        for (int off = 16; off; off >>= 1) acc[h] += __shfl_xor_sync(0xffffffffu, acc[h], off);
    if (lane == 0) {
#pragma unroll
        for (int h = 0; h < NH; h++)
            g_logits[((size_t)b * NH + h) * RR + t] = (acc[h] + g_cb[b * NH + h]) * 0.125f;
    }
}

// softmax over 128 keys, then y[b,h,:] = sum_t w_t * x_t   grid (6,16), 256 thr
__global__ void k_smax_y(const float* __restrict__ hid) {
    int h = blockIdx.x, b = blockIdx.y, t = threadIdx.x;
    __shared__ float w[RR];
    __shared__ int su[RR];
    __shared__ float red[8];
    if (t < RR) {
        w[t] = g_logits[((size_t)b * NH + h) * RR + t];
        su[t] = g_unp[b * RR + t];
    }
    __syncthreads();
    if (t < RR) {
        float m = w[t];
        for (int off = 16; off; off >>= 1) m = fmaxf(m, __shfl_xor_sync(0xffffffffu, m, off));
        if ((t & 31) == 0) red[t >> 5] = m;
    }
    __syncthreads();
    float mx = fmaxf(fmaxf(red[0], red[1]), fmaxf(red[2], red[3]));
    float e = 0.f;
    if (t < RR) e = expf(w[t] - mx);
    float s = e;
    for (int off = 16; off; off >>= 1) s += __shfl_xor_sync(0xffffffffu, s, off);
    if (t < RR && (t & 31) == 0) red[4 + (t >> 5)] = s;
    __syncthreads();
    float tot = red[4] + red[5] + red[6] + red[7];
    if (t < RR) w[t] = e / tot;
    __syncthreads();
    for (int d = t; d < DD; d += 256) {
        float acc = 0.f;
#pragma unroll 4
        for (int tt = 0; tt < RR; tt++)
            acc += w[tt] * hid[((size_t)b * LL + su[tt]) * DD + d];
        g_y[((size_t)b * NH + h) * DD + d] = acc;
    }
}

// ctx partials: grid (16, 4), 384 threads; chunk c covers 192 of the 768 d's.
__global__ void k_ctx(const float* __restrict__ Wv, const float* __restrict__ bv) {
    int b = blockIdx.x, c = blockIdx.y, u = threadIdx.x;
    __shared__ float sy[NH * 192];
    for (int i = u; i < NH * 192; i += UU) {
        int h = i / 192, dd = i % 192;
        sy[i] = g_y[((size_t)b * NH + h) * DD + c * 192 + dd];
    }
    __syncthreads();
    int h = u >> 6;
    float acc = (c == 0) ? bv[u] : 0.f;
    const float* wv = Wv + (size_t)(c * 192) * UU + u;
#pragma unroll 4
    for (int dd = 0; dd < 192; dd++) acc += sy[h * 192 + dd] * wv[(size_t)dd * UU];
    g_ctxp[c][b * UU + u] = acc;
}

// new_token: grid (16, 6), 128 threads; sums 4 ctx partials, then GEMV.
__global__ void k_newtok(const float* __restrict__ Wo, const float* __restrict__ bo,
                         float* __restrict__ out) {
    int b = blockIdx.x, seg = blockIdx.y, t = threadIdx.x;
    __shared__ float sc[UU];
    for (int i = t; i < UU; i += 128)
        sc[i] = g_ctxp[0][b * UU + i] + g_ctxp[1][b * UU + i] +
                g_ctxp[2][b * UU + i] + g_ctxp[3][b * UU + i];
    __syncthreads();
    int d = seg * 128 + t;
    float acc = bo[d];
#pragma unroll 4
    for (int u = 0; u < UU; u++) acc += sc[u] * Wo[(size_t)u * DD + d];
    out[((size_t)b * OT + 385) * DD + d] = acc;
}

// ---------------- launch ----------------------------------------------------
extern "C" void kernel_launch(void* const* d_in, const int* in_sizes, int n_in,
                              void* d_out, int out_size) {
    (void)in_sizes; (void)n_in; (void)out_size;
    const float* hid = (const float*)d_in[0];
    const float* sc  = (const float*)d_in[1];
    const float* Wq  = (const float*)d_in[2];
    const float* bq  = (const float*)d_in[3];
    const float* Wk  = (const float*)d_in[4];
    const float* bk  = (const float*)d_in[5];
    const float* Wv  = (const float*)d_in[6];
    const float* bv  = (const float*)d_in[7];
    const float* Wo  = (const float*)d_in[8];
    const float* bo  = (const float*)d_in[9];
    float* out = (float*)d_out;

    k_init<<<32, 256>>>();
    k_importance<<<dim3(8, HH, BB), 128>>>(sc);
    k_invnorm<<<dim3(64, BB), 256>>>(hid);
    k_topk<<<BB, 512>>>();
    k_sim<<<dim3(4, 4, BB), 256>>>(hid);
    k_edges<<<BB, 256>>>();
    k_copy<<<dim3(129, BB), 192>>>(hid, out);
    k_merge2<<<dim3(LH, BB), 192>>>(hid, out);
    k_qm<<<dim3(NH, BB), 256>>>(hid, Wq, bq, Wk, bk);
    k_logits<<<256, 256>>>(hid);
    k_smax_y<<<dim3(NH, BB), 256>>>(hid);
    k_ctx<<<dim3(BB, 4), 384>>>(Wv, bv);
    k_newtok<<<dim3(BB, 6), 128>>>(Wo, bo, out);
}

// round 16
// speedup vs baseline: 1.3239x; 1.3237x over previous
#include <cuda_runtime.h>
#include <cstdint>

// Problem constants
#define BB 16
#define LL 512
#define DD 768
#define HH 12
#define UU 384
#define NH 6
#define HD 64
#define KP 384
#define RR 128        // L - K  (merged count == unpreserved count)
#define LH 256        // L/2
#define OT 386        // output tokens per batch

// ---------------- device scratch (static, allocation-free) ----------------
__device__ float              g_impp[BB * HH * 4 * LL];   // importance partials
__device__ float              g_invn[BB * LL];
__device__ int                g_unp[BB * RR];
__device__ unsigned long long g_nodekey[BB * LH];
__device__ int                g_unm[BB * RR];
__device__ int                g_csr_off[BB * (LH + 1)];
__device__ int                g_csr_src[BB * RR];
__device__ float              g_m[BB * NH * DD];
__device__ float              g_cb[BB * NH];
__device__ float              g_logits[BB * NH * RR];
__device__ float              g_y[BB * NH * DD];
__device__ float              g_ctxp[4][BB * UU];

__device__ __forceinline__ unsigned ford(float f) {
    unsigned u = __float_as_uint(f);
    return (u & 0x80000000u) ? ~u : (u | 0x80000000u);
}

// packed fp32x2 FMA (sm_100+): acc = a*b + acc, two lanes per instruction
__device__ __forceinline__ void ffma2(unsigned long long& acc,
                                      unsigned long long a, unsigned long long b) {
    asm("fma.rn.f32x2 %0, %1, %2, %0;" : "+l"(acc) : "l"(a), "l"(b));
}
__device__ __forceinline__ unsigned long long pk2(float x, float y) {
    unsigned long long r;
    asm("mov.b64 %0, {%1, %2};" : "=l"(r) : "f"(x), "f"(y));
    return r;
}
__device__ __forceinline__ float lo32(unsigned long long v) {
    return __uint_as_float((unsigned)v);
}
__device__ __forceinline__ float hi32(unsigned long long v) {
    return __uint_as_float((unsigned)(v >> 32));
}

// ---------------- importance partials (no atomics, no init) ----------------
// grid (4 row-chunks, 12 heads, 16 batch), 128 threads (4 cols each)
__global__ void k_importance(const float* __restrict__ sc) {
    int b = blockIdx.z, h = blockIdx.y, c = blockIdx.x;
    int j0 = threadIdx.x * 4;
    const float* base = sc + (((size_t)b * HH + h) * LL + (size_t)c * 128) * LL;
    int i0 = c * 128;
    float a0 = 0.f, a1 = 0.f, a2 = 0.f, a3 = 0.f;
#pragma unroll 4
    for (int i = 0; i < 128; i++) {
        float4 v = *(const float4*)(base + (size_t)i * LL + j0);
        int gi = i0 + i;
        if (gi == j0)     v.x = 0.f;
        if (gi == j0 + 1) v.y = 0.f;
        if (gi == j0 + 2) v.z = 0.f;
        if (gi == j0 + 3) v.w = 0.f;
        a0 += v.x; a1 += v.y; a2 += v.z; a3 += v.w;
    }
    float4 st = make_float4(a0, a1, a2, a3);
    *(float4*)(g_impp + (((size_t)b * HH + h) * 4 + c) * LL + j0) = st;
}

// ---------------- per-token inverse L2 norms + nodekey zeroing -------------
__global__ void k_invnorm(const float* __restrict__ hid) {
    int warp = threadIdx.x >> 5, lane = threadIdx.x & 31;
    int row = blockIdx.x * 8 + warp;
    int b = blockIdx.y;
    int gid = (b * 64 + blockIdx.x) * 256 + threadIdx.x;
    if (gid < BB * LH) g_nodekey[gid] = 0ull;
    const float4* p = (const float4*)(hid + ((size_t)b * LL + row) * DD);
    float s = 0.f;
#pragma unroll
    for (int it = 0; it < 6; it++) {
        float4 v = p[lane + it * 32];
        s += v.x * v.x + v.y * v.y + v.z * v.z + v.w * v.w;
    }
    for (int off = 16; off; off >>= 1) s += __shfl_xor_sync(0xffffffffu, s, off);
    if (lane == 0) g_invn[b * LL + row] = rsqrtf(s);
}

// ---------------- top-K -> unpreserved idx (ascending) ---------------------
// 1024 threads: half-split partial reduction and half-split rank scan.
// Rank-by-count with index tiebreak == lax.top_k; ballot-based compaction.
__global__ void k_topk() {
    int b = blockIdx.x, t = threadIdx.x;
    __shared__ __align__(16) unsigned long long keys[LL];
    __shared__ float hsum[2][LL];
    __shared__ int rcnt[1024];
    __shared__ int wsum[16];
    int j = t & 511, half = t >> 9;
    // sum 24 of the 48 importance partials per half
    {
        const float* pp = g_impp + (size_t)b * 48 * LL + (size_t)half * 24 * LL + j;
        float s = 0.f;
#pragma unroll
        for (int p = 0; p < 24; p++) s += pp[(size_t)p * LL];
        hsum[half][j] = s;
    }
    __syncthreads();
    if (t < LL) {
        float v = hsum[0][t] + hsum[1][t];
        keys[t] = ((unsigned long long)ford(v) << 32) | (unsigned)(0xFFFFFFFFu - t);
    }
    __syncthreads();
    unsigned long long mykey = keys[j];
    int cnt = 0;
    const ulonglong2* k2 = (const ulonglong2*)(keys + half * 256);
#pragma unroll 8
    for (int x = 0; x < 128; x++) {
        ulonglong2 kk = k2[x];
        cnt += (kk.x > mykey) + (kk.y > mykey);
    }
    rcnt[t] = cnt;
    __syncthreads();
    if (t < LL) {
        int rank = rcnt[t] + rcnt[t + 512];
        int unp = (rank >= KP) ? 1 : 0;
        unsigned bal = __ballot_sync(0xffffffffu, unp);
        int lane = t & 31, wp = t >> 5;
        if (lane == 0) wsum[wp] = __popc(bal);
        __syncthreads();
        if (unp) {
            int base = 0;
            for (int w = 0; w < wp; w++) base += wsum[w];
            int pos = base + __popc(bal & ((1u << lane) - 1));
            g_unp[b * RR + pos] = t;
        }
    } else {
        __syncthreads();
    }
}

// ---------------- cosine-sim GEMM + row max/argmax -------------------------
// 64x64 tile, 256 threads, 4x4 micro-tile in packed fp32x2 (exact fp32 fma
// per element — rank decisions identical to scalar). Row argmax via atomicMax.
__global__ void k_sim(const float* __restrict__ hid) {
    int b = blockIdx.z, i0 = blockIdx.y * 64, j0 = blockIdx.x * 64;
    __shared__ __align__(16) float As[16][68];
    __shared__ __align__(16) float Bs[16][68];
    int tid = threadIdx.x;
    int tx = tid & 15, ty = tid >> 4;
    int lrow = tid >> 2, lseg = tid & 3;
    const float* base = hid + (size_t)b * LL * DD;
    float ia = g_invn[b * LL + 2 * (i0 + lrow)];
    float ib = g_invn[b * LL + 2 * (j0 + lrow) + 1];
    const float* arow = base + (size_t)(2 * (i0 + lrow)) * DD + lseg * 4;
    const float* brow = base + (size_t)(2 * (j0 + lrow) + 1) * DD + lseg * 4;

    unsigned long long acc2[2][4];
#pragma unroll
    for (int p = 0; p < 2; p++)
#pragma unroll
        for (int q = 0; q < 4; q++) acc2[p][q] = 0ull;

    for (int k0 = 0; k0 < DD; k0 += 16) {
        float4 av = *(const float4*)(arow + k0);
        float4 bv = *(const float4*)(brow + k0);
        __syncthreads();
        As[lseg * 4 + 0][lrow] = av.x * ia;
        As[lseg * 4 + 1][lrow] = av.y * ia;
        As[lseg * 4 + 2][lrow] = av.z * ia;
        As[lseg * 4 + 3][lrow] = av.w * ia;
        Bs[lseg * 4 + 0][lrow] = bv.x * ib;
        Bs[lseg * 4 + 1][lrow] = bv.y * ib;
        Bs[lseg * 4 + 2][lrow] = bv.z * ib;
        Bs[lseg * 4 + 3][lrow] = bv.w * ib;
        __syncthreads();
#pragma unroll
        for (int kk = 0; kk < 16; kk++) {
            ulonglong2 ap = *(const ulonglong2*)&As[kk][ty * 4];
            float4 c4 = *(const float4*)&Bs[kk][tx * 4];
            unsigned long long c0 = pk2(c4.x, c4.x);
            unsigned long long c1 = pk2(c4.y, c4.y);
            unsigned long long c2 = pk2(c4.z, c4.z);
            unsigned long long c3 = pk2(c4.w, c4.w);
            ffma2(acc2[0][0], ap.x, c0); ffma2(acc2[1][0], ap.y, c0);
            ffma2(acc2[0][1], ap.x, c1); ffma2(acc2[1][1], ap.y, c1);
            ffma2(acc2[0][2], ap.x, c2); ffma2(acc2[1][2], ap.y, c2);
            ffma2(acc2[0][3], ap.x, c3); ffma2(acc2[1][3], ap.y, c3);
        }
    }
#pragma unroll
    for (int r = 0; r < 4; r++) {
        int p = r >> 1;
        float v0, v1, v2, v3;
        if (r & 1) {
            v0 = hi32(acc2[p][0]); v1 = hi32(acc2[p][1]);
            v2 = hi32(acc2[p][2]); v3 = hi32(acc2[p][3]);
        } else {
            v0 = lo32(acc2[p][0]); v1 = lo32(acc2[p][1]);
            v2 = lo32(acc2[p][2]); v3 = lo32(acc2[p][3]);
        }
        float best = v0; int bc = 0;
        if (v1 > best) { best = v1; bc = 1; }
        if (v2 > best) { best = v2; bc = 2; }
        if (v3 > best) { best = v3; bc = 3; }
        int j = j0 + tx * 4 + bc;
        unsigned long long key =
            ((unsigned long long)ford(best) << 32) | (unsigned)(255 - j);
        for (int off = 8; off; off >>= 1) {
            unsigned long long o = __shfl_xor_sync(0xffffffffu, key, off);
            if (o > key) key = o;
        }
        if (tx == 0) atomicMax(&g_nodekey[b * LH + i0 + ty * 4 + r], key);
    }
}

// ---------------- edge argsort + CSR inverse map (warp-scan prefix) --------
__global__ void k_edges() {
    int b = blockIdx.x, i = threadIdx.x;
    __shared__ __align__(16) unsigned long long ek[LH];
    __shared__ int scnt[LH];
    __shared__ int soff[LH];
    __shared__ int scur[LH];
    __shared__ int wtot[8], wbase[8];
    unsigned long long nk = g_nodekey[b * LH + i];
    int nidx = 255 - (int)(unsigned)(nk & 0xFFFFFFFFull);
    unsigned long long key = (nk & 0xFFFFFFFF00000000ull) | (unsigned)(255 - i);
    ek[i] = key;
    scnt[i] = 0;
    scur[i] = 0;
    __syncthreads();
    int rank = 0;
    const ulonglong2* k2 = (const ulonglong2*)ek;
#pragma unroll 8
    for (int x = 0; x < LH / 2; x++) {
        ulonglong2 kk = k2[x];
        rank += (kk.x > key) + (kk.y > key);
    }
    bool issrc = (rank < RR);
    if (issrc) atomicAdd(&scnt[nidx], 1);
    else g_unm[b * RR + (rank - RR)] = i;
    __syncthreads();
    int v = scnt[i];
    int lane = i & 31, wp = i >> 5;
    int incl = v;
#pragma unroll
    for (int o = 1; o < 32; o <<= 1) {
        int n = __shfl_up_sync(0xffffffffu, incl, o);
        if (lane >= o) incl += n;
    }
    if (lane == 31) wtot[wp] = incl;
    __syncthreads();
    if (i == 0) {
        int run = 0;
        for (int w = 0; w < 8; w++) { wbase[w] = run; run += wtot[w]; }
    }
    __syncthreads();
    int excl = incl - v + wbase[wp];
    soff[i] = excl;
    g_csr_off[b * (LH + 1) + i] = excl;
    if (i == 0) g_csr_off[b * (LH + 1) + LH] = RR;
    __syncthreads();
    if (issrc) {
        int slot = atomicAdd(&scur[nidx], 1);
        g_csr_src[b * RR + soff[nidx] + slot] = i;
    }
}

// ---------------- assemble: class + unm copies + CSR merge (fused) ---------
__global__ void k_copymerge(const float* __restrict__ hid, float* __restrict__ out) {
    int b = blockIdx.y, v = blockIdx.x;                  // 0..384
    int d0 = threadIdx.x * 4;
    if (v < 129) {
        int srow = (v == 0) ? 0 : 2 * g_unm[b * RR + (v - 1)];
        float4 s = *(const float4*)(hid + ((size_t)b * LL + srow) * DD + d0);
        *(float4*)(out + ((size_t)b * OT + v) * DD + d0) = s;
    } else {
        int j = v - 129;                                 // 0..255
        int o0 = g_csr_off[b * (LH + 1) + j];
        int o1 = g_csr_off[b * (LH + 1) + j + 1];
        float4 a = *(const float4*)(hid + ((size_t)b * LL + 2 * j + 1) * DD + d0);
        for (int p = o0; p < o1; p++) {
            int s = g_csr_src[b * RR + p];
            float4 x = *(const float4*)(hid + ((size_t)b * LL + 2 * s) * DD + d0);
            a.x += x.x; a.y += x.y; a.z += x.z; a.w += x.w;
        }
        float inv = 1.0f / (float)(1 + (o1 - o0));
        a.x *= inv; a.y *= inv; a.z *= inv; a.w *= inv;
        *(float4*)(out + ((size_t)b * OT + 129 + j) * DD + d0) = a;
    }
}

// ---------------- attention: q_h + m_h + cbias fused, grid (6,16) ----------
__global__ void k_qm(const float* __restrict__ hid, const float* __restrict__ Wq,
                     const float* __restrict__ bq, const float* __restrict__ Wk,
                     const float* __restrict__ bk) {
    int h = blockIdx.x, b = blockIdx.y, t = threadIdx.x;     // 256 threads
    __shared__ float cls[DD];
    __shared__ float qp[4][HD];
    __shared__ float sq[HD];
    __shared__ float sp[HD];
    cls[t] = hid[(size_t)b * LL * DD + t];
    cls[t + 256] = hid[(size_t)b * LL * DD + 256 + t];
    cls[t + 512] = hid[(size_t)b * LL * DD + 512 + t];
    __syncthreads();
    {
        int u = t & 63, kq = t >> 6;
        float p = 0.f;
        const float* wcol = Wq + (size_t)(h * HD + u);
#pragma unroll 4
        for (int k = kq * 192; k < kq * 192 + 192; k++)
            p += cls[k] * wcol[(size_t)k * UU];
        qp[kq][u] = p;
    }
    __syncthreads();
    if (t < HD) {
        float q = bq[h * HD + t] + qp[0][t] + qp[1][t] + qp[2][t] + qp[3][t];
        sq[t] = q;
        sp[t] = q * bk[h * HD + t];
    }
    __syncthreads();
#pragma unroll
    for (int rr = 0; rr < 3; rr++) {
        int row = t + rr * 256;
        const float* wrow = Wk + (size_t)row * UU + h * HD;
        float acc = 0.f;
#pragma unroll
        for (int u = 0; u < HD; u += 4) {
            float4 wv = *(const float4*)(wrow + u);
            acc += wv.x * sq[u] + wv.y * sq[u + 1] + wv.z * sq[u + 2] + wv.w * sq[u + 3];
        }
        g_m[((size_t)b * NH + h) * DD + row] = acc;
    }
    if (t == 0) {
        float c = 0.f;
        for (int u = 0; u < HD; u++) c += sp[u];
        g_cb[b * NH + h] = c;
    }
}

// logits[b,h,t] = (x_t . m_bh + cbias) / 8      one warp per (b,t)
__global__ void k_logits(const float* __restrict__ hid) {
    int w = (blockIdx.x * blockDim.x + threadIdx.x) >> 5;
    int lane = threadIdx.x & 31;
    if (w >= BB * RR) return;
    int b = w >> 7, t = w & 127;
    int row = g_unp[b * RR + t];
    const float* x = hid + ((size_t)b * LL + row) * DD;
    const float* m = g_m + (size_t)b * NH * DD;
    float acc[NH] = {};
    for (int k = lane; k < DD; k += 32) {
        float xv = x[k];
#pragma unroll
        for (int h = 0; h < NH; h++) acc[h] += xv * m[h * DD + k];
    }
#pragma unroll
    for (int h = 0; h < NH; h++)
        for (int off = 16; off; off >>= 1) acc[h] += __shfl_xor_sync(0xffffffffu, acc[h], off);
    if (lane == 0) {
#pragma unroll
        for (int h = 0; h < NH; h++)
            g_logits[((size_t)b * NH + h) * RR + t] = (acc[h] + g_cb[b * NH + h]) * 0.125f;
    }
}

// softmax over 128 keys, then y[b,h,:] = sum_t w_t * x_t   grid (6,16), 256 thr
__global__ void k_smax_y(const float* __restrict__ hid) {
    int h = blockIdx.x, b = blockIdx.y, t = threadIdx.x;
    __shared__ float w[RR];
    __shared__ int su[RR];
    __shared__ float red[8];
    if (t < RR) {
        w[t] = g_logits[((size_t)b * NH + h) * RR + t];
        su[t] = g_unp[b * RR + t];
    }
    __syncthreads();
    if (t < RR) {
        float m = w[t];
        for (int off = 16; off; off >>= 1) m = fmaxf(m, __shfl_xor_sync(0xffffffffu, m, off));
        if ((t & 31) == 0) red[t >> 5] = m;
    }
    __syncthreads();
    float mx = fmaxf(fmaxf(red[0], red[1]), fmaxf(red[2], red[3]));
    float e = 0.f;
    if (t < RR) e = expf(w[t] - mx);
    float s = e;
    for (int off = 16; off; off >>= 1) s += __shfl_xor_sync(0xffffffffu, s, off);
    if (t < RR && (t & 31) == 0) red[4 + (t >> 5)] = s;
    __syncthreads();
    float tot = red[4] + red[5] + red[6] + red[7];
    if (t < RR) w[t] = e / tot;
    __syncthreads();
    for (int d = t; d < DD; d += 256) {
        float acc = 0.f;
#pragma unroll 4
        for (int tt = 0; tt < RR; tt++)
            acc += w[tt] * hid[((size_t)b * LL + su[tt]) * DD + d];
        g_y[((size_t)b * NH + h) * DD + d] = acc;
    }
}

// ctx partials: grid (16, 4), 384 threads; chunk c covers 192 of the 768 d's.
__global__ void k_ctx(const float* __restrict__ Wv, const float* __restrict__ bv) {
    int b = blockIdx.x, c = blockIdx.y, u = threadIdx.x;
    __shared__ float sy[NH * 192];
    for (int i = u; i < NH * 192; i += UU) {
        int h = i / 192, dd = i % 192;
        sy[i] = g_y[((size_t)b * NH + h) * DD + c * 192 + dd];
    }
    __syncthreads();
    int h = u >> 6;
    float acc = (c == 0) ? bv[u] : 0.f;
    const float* wv = Wv + (size_t)(c * 192) * UU + u;
#pragma unroll 4
    for (int dd = 0; dd < 192; dd++) acc += sy[h * 192 + dd] * wv[(size_t)dd * UU];
    g_ctxp[c][b * UU + u] = acc;
}

// new_token: grid (16, 6), 128 threads; sums 4 ctx partials, then GEMV.
__global__ void k_newtok(const float* __restrict__ Wo, const float* __restrict__ bo,
                         float* __restrict__ out) {
    int b = blockIdx.x, seg = blockIdx.y, t = threadIdx.x;
    __shared__ float sc[UU];
    for (int i = t; i < UU; i += 128)
        sc[i] = g_ctxp[0][b * UU + i] + g_ctxp[1][b * UU + i] +
                g_ctxp[2][b * UU + i] + g_ctxp[3][b * UU + i];
    __syncthreads();
    int d = seg * 128 + t;
    float acc = bo[d];
#pragma unroll 4
    for (int u = 0; u < UU; u++) acc += sc[u] * Wo[(size_t)u * DD + d];
    out[((size_t)b * OT + 385) * DD + d] = acc;
}

// ---------------- launch: fork-join DAG over 3 streams ----------------------
extern "C" void kernel_launch(void* const* d_in, const int* in_sizes, int n_in,
                              void* d_out, int out_size) {
    (void)in_sizes; (void)n_in; (void)out_size;
    const float* hid = (const float*)d_in[0];
    const float* sc  = (const float*)d_in[1];
    const float* Wq  = (const float*)d_in[2];
    const float* bq  = (const float*)d_in[3];
    const float* Wk  = (const float*)d_in[4];
    const float* bk  = (const float*)d_in[5];
    const float* Wv  = (const float*)d_in[6];
    const float* bv  = (const float*)d_in[7];
    const float* Wo  = (const float*)d_in[8];
    const float* bo  = (const float*)d_in[9];
    float* out = (float*)d_out;

    static cudaStream_t sB = nullptr, sC = nullptr;
    static cudaEvent_t eR = nullptr, eB = nullptr, eC = nullptr;
    if (!sB) {  // first call is the (non-captured) correctness run
        cudaStreamCreateWithFlags(&sB, cudaStreamNonBlocking);
        cudaStreamCreateWithFlags(&sC, cudaStreamNonBlocking);
        cudaEventCreateWithFlags(&eR, cudaEventDisableTiming);
        cudaEventCreateWithFlags(&eB, cudaEventDisableTiming);
        cudaEventCreateWithFlags(&eC, cudaEventDisableTiming);
    }

    // fork
    cudaEventRecord(eR, 0);
    cudaStreamWaitEvent(sB, eR, 0);
    cudaStreamWaitEvent(sC, eR, 0);

    // Branch B: token-merge chain (FMA-bound)
    k_invnorm<<<dim3(64, BB), 256, 0, sB>>>(hid);
    k_sim<<<dim3(4, 4, BB), 256, 0, sB>>>(hid);
    k_edges<<<BB, 256, 0, sB>>>();
    k_copymerge<<<dim3(385, BB), 192, 0, sB>>>(hid, out);
    cudaEventRecord(eB, sB);

    // Branch C: q/m projection (independent of importance)
    k_qm<<<dim3(NH, BB), 256, 0, sC>>>(hid, Wq, bq, Wk, bk);
    cudaEventRecord(eC, sC);

    // Branch A (capture stream): importance chain (DRAM-bound)
    k_importance<<<dim3(4, HH, BB), 128>>>(sc);
    k_topk<<<BB, 1024>>>();
    cudaStreamWaitEvent(0, eC, 0);
    k_logits<<<256, 256>>>(hid);
    k_smax_y<<<dim3(NH, BB), 256>>>(hid);
    k_ctx<<<dim3(BB, 4), 384>>>(Wv, bv);
    k_newtok<<<dim3(BB, 6), 128>>>(Wo, bo, out);

    // join
    cudaStreamWaitEvent(0, eB, 0);
}

// round 17
// speedup vs baseline: 1.3497x; 1.0195x over previous
#include <cuda_runtime.h>
#include <cstdint>

// Problem constants
#define BB 16
#define LL 512
#define DD 768
#define HH 12
#define UU 384
#define NH 6
#define HD 64
#define KP 384
#define RR 128        // L - K  (merged count == unpreserved count)
#define LH 256        // L/2
#define OT 386        // output tokens per batch
#define NCH 16        // importance row chunks
#define NP  (HH * NCH)   // 192 importance partials per (b, col)

// ---------------- device scratch (static, allocation-free) ----------------
__device__ float              g_impp[BB * NP * LL];   // importance partials
__device__ float              g_invn[BB * LL];
__device__ unsigned long long g_nodekey[BB * LH];
__device__ int                g_unm[BB * RR];
__device__ int                g_csr_off[BB * (LH + 1)];
__device__ int                g_csr_src[BB * RR];
__device__ float              g_m[BB * NH * DD];
__device__ float              g_cb[BB * NH];

__device__ __forceinline__ unsigned ford(float f) {
    unsigned u = __float_as_uint(f);
    return (u & 0x80000000u) ? ~u : (u | 0x80000000u);
}

// packed fp32x2 FMA (sm_100+): acc = a*b + acc, two lanes per instruction
__device__ __forceinline__ void ffma2(unsigned long long& acc,
                                      unsigned long long a, unsigned long long b) {
    asm("fma.rn.f32x2 %0, %1, %2, %0;" : "+l"(acc) : "l"(a), "l"(b));
}
__device__ __forceinline__ unsigned long long pk2(float x, float y) {
    unsigned long long r;
    asm("mov.b64 %0, {%1, %2};" : "=l"(r) : "f"(x), "f"(y));
    return r;
}
__device__ __forceinline__ float lo32(unsigned long long v) {
    return __uint_as_float((unsigned)v);
}
__device__ __forceinline__ float hi32(unsigned long long v) {
    return __uint_as_float((unsigned)(v >> 32));
}

// ---------------- importance partials (pure stream, diag via subtract) -----
// grid (16 row-chunks, 12 heads, 16 batch), 128 threads (4 cols via float4)
__global__ void k_importance(const float* __restrict__ sc) {
    int b = blockIdx.z, h = blockIdx.y, c = blockIdx.x;
    int j0 = threadIdx.x * 4;
    const float* base = sc + (((size_t)b * HH + h) * LL + (size_t)c * 32) * LL;
    int i0 = c * 32;
    float a0 = 0.f, a1 = 0.f, a2 = 0.f, a3 = 0.f;
#pragma unroll 8
    for (int i = 0; i < 32; i++) {
        float4 v = *(const float4*)(base + (size_t)i * LL + j0);
        a0 += v.x; a1 += v.y; a2 += v.z; a3 += v.w;
    }
    // remove diagonal contribution (cols j0..j0+3 lie wholly in/out of chunk)
    if (j0 >= i0 && j0 < i0 + 32) {
        a0 -= base[(size_t)(j0 - i0) * LL + j0];
        a1 -= base[(size_t)(j0 + 1 - i0) * LL + j0 + 1];
        a2 -= base[(size_t)(j0 + 2 - i0) * LL + j0 + 2];
        a3 -= base[(size_t)(j0 + 3 - i0) * LL + j0 + 3];
    }
    *(float4*)(g_impp + (((size_t)b * HH + h) * NCH + c) * LL + j0) =
        make_float4(a0, a1, a2, a3);
}

// ---------------- per-token inverse L2 norms + nodekey zeroing -------------
__global__ void k_invnorm(const float* __restrict__ hid) {
    int warp = threadIdx.x >> 5, lane = threadIdx.x & 31;
    int row = blockIdx.x * 8 + warp;
    int b = blockIdx.y;
    int gid = (b * 64 + blockIdx.x) * 256 + threadIdx.x;
    if (gid < BB * LH) g_nodekey[gid] = 0ull;
    const float4* p = (const float4*)(hid + ((size_t)b * LL + row) * DD);
    float s = 0.f;
#pragma unroll
    for (int it = 0; it < 6; it++) {
        float4 v = p[lane + it * 32];
        s += v.x * v.x + v.y * v.y + v.z * v.z + v.w * v.w;
    }
    for (int off = 16; off; off >>= 1) s += __shfl_xor_sync(0xffffffffu, s, off);
    if (lane == 0) g_invn[b * LL + row] = rsqrtf(s);
}

// ---------------- cosine-sim GEMM + row max/argmax -------------------------
__global__ void k_sim(const float* __restrict__ hid) {
    int b = blockIdx.z, i0 = blockIdx.y * 64, j0 = blockIdx.x * 64;
    __shared__ __align__(16) float As[16][68];
    __shared__ __align__(16) float Bs[16][68];
    int tid = threadIdx.x;
    int tx = tid & 15, ty = tid >> 4;
    int lrow = tid >> 2, lseg = tid & 3;
    const float* base = hid + (size_t)b * LL * DD;
    float ia = g_invn[b * LL + 2 * (i0 + lrow)];
    float ib = g_invn[b * LL + 2 * (j0 + lrow) + 1];
    const float* arow = base + (size_t)(2 * (i0 + lrow)) * DD + lseg * 4;
    const float* brow = base + (size_t)(2 * (j0 + lrow) + 1) * DD + lseg * 4;

    unsigned long long acc2[2][4];
#pragma unroll
    for (int p = 0; p < 2; p++)
#pragma unroll
        for (int q = 0; q < 4; q++) acc2[p][q] = 0ull;

    for (int k0 = 0; k0 < DD; k0 += 16) {
        float4 av = *(const float4*)(arow + k0);
        float4 bv = *(const float4*)(brow + k0);
        __syncthreads();
        As[lseg * 4 + 0][lrow] = av.x * ia;
        As[lseg * 4 + 1][lrow] = av.y * ia;
        As[lseg * 4 + 2][lrow] = av.z * ia;
        As[lseg * 4 + 3][lrow] = av.w * ia;
        Bs[lseg * 4 + 0][lrow] = bv.x * ib;
        Bs[lseg * 4 + 1][lrow] = bv.y * ib;
        Bs[lseg * 4 + 2][lrow] = bv.z * ib;
        Bs[lseg * 4 + 3][lrow] = bv.w * ib;
        __syncthreads();
#pragma unroll
        for (int kk = 0; kk < 16; kk++) {
            ulonglong2 ap = *(const ulonglong2*)&As[kk][ty * 4];
            float4 c4 = *(const float4*)&Bs[kk][tx * 4];
            unsigned long long c0 = pk2(c4.x, c4.x);
            unsigned long long c1 = pk2(c4.y, c4.y);
            unsigned long long c2 = pk2(c4.z, c4.z);
            unsigned long long c3 = pk2(c4.w, c4.w);
            ffma2(acc2[0][0], ap.x, c0); ffma2(acc2[1][0], ap.y, c0);
            ffma2(acc2[0][1], ap.x, c1); ffma2(acc2[1][1], ap.y, c1);
            ffma2(acc2[0][2], ap.x, c2); ffma2(acc2[1][2], ap.y, c2);
            ffma2(acc2[0][3], ap.x, c3); ffma2(acc2[1][3], ap.y, c3);
        }
    }
#pragma unroll
    for (int r = 0; r < 4; r++) {
        int p = r >> 1;
        float v0, v1, v2, v3;
        if (r & 1) {
            v0 = hi32(acc2[p][0]); v1 = hi32(acc2[p][1]);
            v2 = hi32(acc2[p][2]); v3 = hi32(acc2[p][3]);
        } else {
            v0 = lo32(acc2[p][0]); v1 = lo32(acc2[p][1]);
            v2 = lo32(acc2[p][2]); v3 = lo32(acc2[p][3]);
        }
        float best = v0; int bc = 0;
        if (v1 > best) { best = v1; bc = 1; }
        if (v2 > best) { best = v2; bc = 2; }
        if (v3 > best) { best = v3; bc = 3; }
        int j = j0 + tx * 4 + bc;
        unsigned long long key =
            ((unsigned long long)ford(best) << 32) | (unsigned)(255 - j);
        for (int off = 8; off; off >>= 1) {
            unsigned long long o = __shfl_xor_sync(0xffffffffu, key, off);
            if (o > key) key = o;
        }
        if (tx == 0) atomicMax(&g_nodekey[b * LH + i0 + ty * 4 + r], key);
    }
}

// ---------------- edge argsort + CSR inverse map (warp-scan prefix) --------
__global__ void k_edges() {
    int b = blockIdx.x, i = threadIdx.x;
    __shared__ __align__(16) unsigned long long ek[LH];
    __shared__ int scnt[LH];
    __shared__ int soff[LH];
    __shared__ int scur[LH];
    __shared__ int wtot[8], wbase[8];
    unsigned long long nk = g_nodekey[b * LH + i];
    int nidx = 255 - (int)(unsigned)(nk & 0xFFFFFFFFull);
    unsigned long long key = (nk & 0xFFFFFFFF00000000ull) | (unsigned)(255 - i);
    ek[i] = key;
    scnt[i] = 0;
    scur[i] = 0;
    __syncthreads();
    int rank = 0;
    const ulonglong2* k2 = (const ulonglong2*)ek;
#pragma unroll 8
    for (int x = 0; x < LH / 2; x++) {
        ulonglong2 kk = k2[x];
        rank += (kk.x > key) + (kk.y > key);
    }
    bool issrc = (rank < RR);
    if (issrc) atomicAdd(&scnt[nidx], 1);
    else g_unm[b * RR + (rank - RR)] = i;
    __syncthreads();
    int v = scnt[i];
    int lane = i & 31, wp = i >> 5;
    int incl = v;
#pragma unroll
    for (int o = 1; o < 32; o <<= 1) {
        int n = __shfl_up_sync(0xffffffffu, incl, o);
        if (lane >= o) incl += n;
    }
    if (lane == 31) wtot[wp] = incl;
    __syncthreads();
    if (i == 0) {
        int run = 0;
        for (int w = 0; w < 8; w++) { wbase[w] = run; run += wtot[w]; }
    }
    __syncthreads();
    int excl = incl - v + wbase[wp];
    soff[i] = excl;
    g_csr_off[b * (LH + 1) + i] = excl;
    if (i == 0) g_csr_off[b * (LH + 1) + LH] = RR;
    __syncthreads();
    if (issrc) {
        int slot = atomicAdd(&scur[nidx], 1);
        g_csr_src[b * RR + soff[nidx] + slot] = i;
    }
}

// ---------------- assemble: class + unm copies + CSR merge (fused) ---------
__global__ void k_copymerge(const float* __restrict__ hid, float* __restrict__ out) {
    int b = blockIdx.y, v = blockIdx.x;                  // 0..384
    int d0 = threadIdx.x * 4;
    if (v < 129) {
        int srow = (v == 0) ? 0 : 2 * g_unm[b * RR + (v - 1)];
        float4 s = *(const float4*)(hid + ((size_t)b * LL + srow) * DD + d0);
        *(float4*)(out + ((size_t)b * OT + v) * DD + d0) = s;
    } else {
        int j = v - 129;                                 // 0..255
        int o0 = g_csr_off[b * (LH + 1) + j];
        int o1 = g_csr_off[b * (LH + 1) + j + 1];
        float4 a = *(const float4*)(hid + ((size_t)b * LL + 2 * j + 1) * DD + d0);
        for (int p = o0; p < o1; p++) {
            int s = g_csr_src[b * RR + p];
            float4 x = *(const float4*)(hid + ((size_t)b * LL + 2 * s) * DD + d0);
            a.x += x.x; a.y += x.y; a.z += x.z; a.w += x.w;
        }
        float inv = 1.0f / (float)(1 + (o1 - o0));
        a.x *= inv; a.y *= inv; a.z *= inv; a.w *= inv;
        *(float4*)(out + ((size_t)b * OT + 129 + j) * DD + d0) = a;
    }
}

// ---------------- attention: q_h + m_h + cbias fused, grid (6,16) ----------
__global__ void k_qm(const float* __restrict__ hid, const float* __restrict__ Wq,
                     const float* __restrict__ bq, const float* __restrict__ Wk,
                     const float* __restrict__ bk) {
    int h = blockIdx.x, b = blockIdx.y, t = threadIdx.x;     // 256 threads
    __shared__ float cls[DD];
    __shared__ float qp[4][HD];
    __shared__ float sq[HD];
    __shared__ float sp[HD];
    cls[t] = hid[(size_t)b * LL * DD + t];
    cls[t + 256] = hid[(size_t)b * LL * DD + 256 + t];
    cls[t + 512] = hid[(size_t)b * LL * DD + 512 + t];
    __syncthreads();
    {
        int u = t & 63, kq = t >> 6;
        float p = 0.f;
        const float* wcol = Wq + (size_t)(h * HD + u);
#pragma unroll 4
        for (int k = kq * 192; k < kq * 192 + 192; k++)
            p += cls[k] * wcol[(size_t)k * UU];
        qp[kq][u] = p;
    }
    __syncthreads();
    if (t < HD) {
        float q = bq[h * HD + t] + qp[0][t] + qp[1][t] + qp[2][t] + qp[3][t];
        sq[t] = q;
        sp[t] = q * bk[h * HD + t];
    }
    __syncthreads();
#pragma unroll
    for (int rr = 0; rr < 3; rr++) {
        int row = t + rr * 256;
        const float* wrow = Wk + (size_t)row * UU + h * HD;
        float acc = 0.f;
#pragma unroll
        for (int u = 0; u < HD; u += 4) {
            float4 wv = *(const float4*)(wrow + u);
            acc += wv.x * sq[u] + wv.y * sq[u + 1] + wv.z * sq[u + 2] + wv.w * sq[u + 3];
        }
        g_m[((size_t)b * NH + h) * DD + row] = acc;
    }
    if (t == 0) {
        float c = 0.f;
        for (int u = 0; u < HD; u++) c += sp[u];
        g_cb[b * NH + h] = c;
    }
}

// ---------------- MEGA: topk + logits + softmax + y + ctx + newtok ---------
// grid 16 (one block per batch), 1024 threads. Everything stays in smem.
__global__ __launch_bounds__(1024, 1)
void k_mega(const float* __restrict__ hid,
            const float* __restrict__ Wv, const float* __restrict__ bv,
            const float* __restrict__ Wo, const float* __restrict__ bo,
            float* __restrict__ out) {
    int b = blockIdx.x, t = threadIdx.x;
    int lane = t & 31, wp = t >> 5;

    // overlay buffer: topk scratch (keys 4K | hsum 4K | rcnt 4K) then y (18K)
    __shared__ __align__(16) unsigned char ubuf[NH * DD * 4];
    unsigned long long* keys = (unsigned long long*)ubuf;          // [512]
    float* hs   = (float*)(ubuf + 4096);                           // [2][512]
    int*   rcnt = (int*)(ubuf + 12288);                            // [1024]
    float* y_s  = (float*)ubuf;                                    // [NH*DD]

    __shared__ float m_s[NH * DD];
    __shared__ float lg[NH][RR];
    __shared__ int   unp[RR];
    __shared__ float cb_s[NH];
    __shared__ int   wsum[32];
    __shared__ float redm[NH][4], reds[NH][4];
    __shared__ float cpart[2][UU];
    __shared__ float ctx_s[UU];

    // preload m (overlaps topk latency)
    for (int i = t; i < NH * DD; i += 1024) m_s[i] = g_m[(size_t)b * NH * DD + i];
    if (t < NH) cb_s[t] = g_cb[b * NH + t];

    // ---- stage T: top-K rank-by-count (half-split) ----
    int j = t & 511, half = t >> 9;
    {
        const float* pp = g_impp + (size_t)b * NP * LL + (size_t)half * (NP / 2) * LL + j;
        float s = 0.f;
#pragma unroll
        for (int p = 0; p < NP / 2; p++) s += pp[(size_t)p * LL];
        hs[half * 512 + j] = s;
    }
    __syncthreads();
    if (t < LL) {
        float v = hs[t] + hs[512 + t];
        keys[t] = ((unsigned long long)ford(v) << 32) | (unsigned)(0xFFFFFFFFu - t);
    }
    __syncthreads();
    unsigned long long mykey = keys[j];
    {
        int cnt = 0;
        const ulonglong2* k2 = (const ulonglong2*)(keys + half * 256);
#pragma unroll 8
        for (int x = 0; x < 128; x++) {
            ulonglong2 kk = k2[x];
            cnt += (kk.x > mykey) + (kk.y > mykey);
        }
        rcnt[t] = cnt;
    }
    __syncthreads();
    int isunp = 0;
    if (t < LL) isunp = (rcnt[t] + rcnt[t + 512] >= KP) ? 1 : 0;
    unsigned bal = __ballot_sync(0xffffffffu, isunp);
    if (lane == 0) wsum[wp] = __popc(bal);
    __syncthreads();
    if (isunp) {
        int base = 0;
        for (int w = 0; w < wp; w++) base += wsum[w];
        int pos = base + __popc(bal & ((1u << lane) - 1));
        unp[pos] = t;
    }
    __syncthreads();

    // ---- stage L: logits[h][t] = (x_t . m_h + cb) / 8 (warp per token) ----
    for (int tt = wp; tt < RR; tt += 32) {
        int row = unp[tt];
        const float* x = hid + ((size_t)b * LL + row) * DD;
        float acc[NH] = {};
        for (int k = lane; k < DD; k += 32) {
            float xv = x[k];
#pragma unroll
            for (int h = 0; h < NH; h++) acc[h] += xv * m_s[h * DD + k];
        }
#pragma unroll
        for (int h = 0; h < NH; h++)
            for (int off = 16; off; off >>= 1)
                acc[h] += __shfl_xor_sync(0xffffffffu, acc[h], off);
        if (lane == 0) {
#pragma unroll
            for (int h = 0; h < NH; h++)
                lg[h][tt] = (acc[h] + cb_s[h]) * 0.125f;
        }
    }
    __syncthreads();

    // ---- stage S: softmax per head (warps 0..23: h = wp/4, tt = (wp%4)*32+lane)
    int sh = wp >> 2, sub = wp & 3, stt = sub * 32 + lane;
    float ve = 0.f, ee = 0.f;
    if (wp < 24) {
        ve = lg[sh][stt];
        float m = ve;
        for (int off = 16; off; off >>= 1)
            m = fmaxf(m, __shfl_xor_sync(0xffffffffu, m, off));
        if (lane == 0) redm[sh][sub] = m;
    }
    __syncthreads();
    if (wp < 24) {
        float mx = fmaxf(fmaxf(redm[sh][0], redm[sh][1]),
                         fmaxf(redm[sh][2], redm[sh][3]));
        ee = expf(ve - mx);
        float s = ee;
        for (int off = 16; off; off >>= 1) s += __shfl_xor_sync(0xffffffffu, s, off);
        if (lane == 0) reds[sh][sub] = s;
    }
    __syncthreads();
    if (wp < 24) {
        float tot = reds[sh][0] + reds[sh][1] + reds[sh][2] + reds[sh][3];
        lg[sh][stt] = ee / tot;
    }
    __syncthreads();

    // ---- stage Y: y[h][d] = sum_t w[h][t] * x[unp[t]][d]  (thread per d) ----
    if (t < DD) {
        float fa[NH] = {};
        for (int tt = 0; tt < RR; tt++) {
            float xv = hid[((size_t)b * LL + unp[tt]) * DD + t];
#pragma unroll
            for (int h = 0; h < NH; h++) fa[h] += lg[h][tt] * xv;
        }
#pragma unroll
        for (int h = 0; h < NH; h++) y_s[h * DD + t] = fa[h];
    }
    __syncthreads();

    // ---- stage C: ctx[u] = bv[u] + y[h(u)] . Wv[:,u]  (k-split 2) ----
    if (t < 768) {
        int part = (t < UU) ? 0 : 1;
        int u = t - part * UU;
        int h = u >> 6;
        const float* wv = Wv + (size_t)(part * 384) * UU + u;
        const float* yy = y_s + h * DD + part * 384;
        float acc = 0.f;
#pragma unroll 4
        for (int dd = 0; dd < 384; dd++) acc += yy[dd] * wv[(size_t)dd * UU];
        cpart[part][u] = acc;
    }
    __syncthreads();
    if (t < UU) ctx_s[t] = bv[t] + cpart[0][t] + cpart[1][t];
    __syncthreads();

    // ---- stage O: new_token = ctx @ Wo + bo -> out row 385 ----
    if (t < DD) {
        float acc = bo[t];
#pragma unroll 4
        for (int u = 0; u < UU; u++) acc += ctx_s[u] * Wo[(size_t)u * DD + t];
        out[((size_t)b * OT + 385) * DD + t] = acc;
    }
}

// ---------------- launch: fork-join DAG over 3 streams ----------------------
extern "C" void kernel_launch(void* const* d_in, const int* in_sizes, int n_in,
                              void* d_out, int out_size) {
    (void)in_sizes; (void)n_in; (void)out_size;
    const float* hid = (const float*)d_in[0];
    const float* sc  = (const float*)d_in[1];
    const float* Wq  = (const float*)d_in[2];
    const float* bq  = (const float*)d_in[3];
    const float* Wk  = (const float*)d_in[4];
    const float* bk  = (const float*)d_in[5];
    const float* Wv  = (const float*)d_in[6];
    const float* bv  = (const float*)d_in[7];
    const float* Wo  = (const float*)d_in[8];
    const float* bo  = (const float*)d_in[9];
    float* out = (float*)d_out;

    static cudaStream_t sB = nullptr, sC = nullptr;
    static cudaEvent_t eR = nullptr, eB = nullptr, eC = nullptr;
    if (!sB) {  // first call is the (non-captured) correctness run
        cudaStreamCreateWithFlags(&sB, cudaStreamNonBlocking);
        cudaStreamCreateWithFlags(&sC, cudaStreamNonBlocking);
        cudaEventCreateWithFlags(&eR, cudaEventDisableTiming);
        cudaEventCreateWithFlags(&eB, cudaEventDisableTiming);
        cudaEventCreateWithFlags(&eC, cudaEventDisableTiming);
    }

    // fork
    cudaEventRecord(eR, 0);
    cudaStreamWaitEvent(sB, eR, 0);
    cudaStreamWaitEvent(sC, eR, 0);

    // Branch B: token-merge chain (FMA-bound)
    k_invnorm<<<dim3(64, BB), 256, 0, sB>>>(hid);
    k_sim<<<dim3(4, 4, BB), 256, 0, sB>>>(hid);
    k_edges<<<BB, 256, 0, sB>>>();
    k_copymerge<<<dim3(385, BB), 192, 0, sB>>>(hid, out);
    cudaEventRecord(eB, sB);

    // Branch C: q/m projection (independent of importance)
    k_qm<<<dim3(NH, BB), 256, 0, sC>>>(hid, Wq, bq, Wk, bk);
    cudaEventRecord(eC, sC);

    // Branch A (capture stream): importance stream -> fused attention tail
    k_importance<<<dim3(NCH, HH, BB), 128>>>(sc);
    cudaStreamWaitEvent(0, eC, 0);
    k_mega<<<BB, 1024>>>(hid, Wv, bv, Wo, bo, out);

    // join
    cudaStreamWaitEvent(0, eB, 0);
}